// round 4
// baseline (speedup 1.0000x reference)
#include <cuda_runtime.h>
#include <cuda_bf16.h>
#include <math.h>
#include <stdint.h>

#define B_   64
#define L_   1024
#define ENC_ 2048
#define DEC_ 512
#define ATT_ 512
#define BL_  (B_ * L_)

// ---------------------------------------------------------------------------
// Device scratch
// ---------------------------------------------------------------------------
__device__ float g_H[B_ * ATT_];                             // proj_h + b2 + b1
// W1 split into bf16 hi/lo, layout [kchunk c][n 512][k 32] (K-major per chunk)
__device__ __align__(128) __nv_bfloat16 g_Bhi[ENC_ * ATT_];
__device__ __align__(128) __nv_bfloat16 g_Blo[ENC_ * ATT_];
__device__ float g_scorep[2 * BL_];                          // per-N-half score partials
__device__ float g_ctxp[8 * B_ * ENC_];                      // context partials

// ---------------------------------------------------------------------------
// Helpers
// ---------------------------------------------------------------------------
__device__ __forceinline__ uint32_t smem_u32(const void* p) {
    uint32_t a;
    asm("{ .reg .u64 t; cvta.to.shared.u64 t, %1; cvt.u32.u64 %0, t; }" : "=r"(a) : "l"(p));
    return a;
}
__device__ __forceinline__ void cp16(uint32_t dst, const void* src) {
    asm volatile("cp.async.cg.shared.global [%0], [%1], 16;" :: "r"(dst), "l"(src));
}
__device__ __forceinline__ void cp_commit() {
    asm volatile("cp.async.commit_group;" ::: "memory");
}
__device__ __forceinline__ void cp_wait0() {
    asm volatile("cp.async.wait_group 0;" ::: "memory");
}
__device__ __forceinline__ void ldsm_x4(uint32_t* r, uint32_t addr) {
    asm volatile("ldmatrix.sync.aligned.m8n8.x4.shared.b16 {%0,%1,%2,%3}, [%4];"
                 : "=r"(r[0]), "=r"(r[1]), "=r"(r[2]), "=r"(r[3]) : "r"(addr));
}
__device__ __forceinline__ void ldsm_x2(uint32_t* r, uint32_t addr) {
    asm volatile("ldmatrix.sync.aligned.m8n8.x2.shared.b16 {%0,%1}, [%2];"
                 : "=r"(r[0]), "=r"(r[1]) : "r"(addr));
}
__device__ __forceinline__ void mma_bf16(float* d, const uint32_t* a, const uint32_t* b) {
    asm volatile(
        "mma.sync.aligned.m16n8k16.row.col.f32.bf16.bf16.f32 "
        "{%0,%1,%2,%3}, {%4,%5,%6,%7}, {%8,%9}, {%0,%1,%2,%3};"
        : "+f"(d[0]), "+f"(d[1]), "+f"(d[2]), "+f"(d[3])
        : "r"(a[0]), "r"(a[1]), "r"(a[2]), "r"(a[3]), "r"(b[0]), "r"(b[1]));
}
__device__ __forceinline__ float fast_tanh(float x) {
    float e = __expf(2.f * x);
    return __fdividef(e - 1.f, e + 1.f);
}

// ---------------------------------------------------------------------------
// Kernel A: H = hidden @ W2 + b2 + b1
// ---------------------------------------------------------------------------
__global__ void proj_h_kernel(const float* __restrict__ hidden,
                              const float* __restrict__ W2,
                              const float* __restrict__ b2,
                              const float* __restrict__ b1) {
    __shared__ float hs[DEC_];
    int b = blockIdx.x, a = threadIdx.x;
    hs[a] = hidden[b * DEC_ + a];
    __syncthreads();
    float acc = 0.f;
#pragma unroll 8
    for (int d = 0; d < DEC_; ++d) acc += hs[d] * W2[d * ATT_ + a];
    g_H[b * ATT_ + a] = acc + b2[a] + b1[a];
}

// ---------------------------------------------------------------------------
// Kernel B: split W1 [ENC, ATT] fp32 -> bf16 hi/lo, layout [c][n][k32]
// ---------------------------------------------------------------------------
__global__ void prep_B_kernel(const float* __restrict__ W1) {
    int idx = blockIdx.x * 256 + threadIdx.x;   // idx = k*512 + n
    if (idx >= ENC_ * ATT_) return;
    int k = idx >> 9, n = idx & 511;
    float x = W1[idx];
    __nv_bfloat16 h = __float2bfloat16(x);
    __nv_bfloat16 l = __float2bfloat16(x - __bfloat162float(h));
    int c = k >> 5, kk = k & 31;
    size_t o = ((size_t)(c * 512 + n) << 5) + kk;
    g_Bhi[o] = h;
    g_Blo[o] = l;
}

// ---------------------------------------------------------------------------
// Kernel C: fused bf16x3 mma.sync GEMM + tanh + V-reduction -> score partials
// Grid: (2 n-halves, 512 m-tiles). CTA: 128x256 tile, 512 thr, K staged x2.
// ---------------------------------------------------------------------------
static constexpr int KC      = 32;
static constexpr int PITCH   = 80;            // bytes per row (32 bf16 + 8 pad)
static constexpr int A_SZ    = 128 * PITCH;   // 10240
static constexpr int B_SZ    = 256 * PITCH;   // 20480
static constexpr int STAGE   = 2 * A_SZ + 2 * B_SZ;  // 61440
static constexpr int OFF_AHI = 0;
static constexpr int OFF_ALO = A_SZ;
static constexpr int OFF_BHI = 2 * A_SZ;
static constexpr int OFF_BLO = 2 * A_SZ + B_SZ;
static constexpr int OFF_PART = 2 * STAGE;            // 122880: 4*128 floats
static constexpr int OFF_H    = OFF_PART + 2048;      // 256 floats
static constexpr int OFF_V    = OFF_H + 1024;         // 256 floats
static constexpr int SMEM_TOTAL = OFF_V + 1024;       // 126976

__global__ __launch_bounds__(512, 1) void score_mma_kernel(
    const float* __restrict__ F,
    const float* __restrict__ V)
{
    extern __shared__ char smem[];
    const uint32_t sb = smem_u32(smem);
    const int tid  = threadIdx.x;
    const int lane = tid & 31;
    const int wid  = tid >> 5;
    const int wm   = wid & 3;        // warp m: 4 x 32 rows
    const int wn   = wid >> 2;       // warp n: 4 x 64 cols
    const int nc   = blockIdx.x;     // n half (256 cols)
    const int m0   = blockIdx.y * 128;
    const int b    = blockIdx.y >> 3;

    float* partS = (float*)(smem + OFF_PART);
    float* Hs    = (float*)(smem + OFF_H);
    float* Vs    = (float*)(smem + OFF_V);
    if (tid < 256) {
        Hs[tid] = g_H[b * ATT_ + nc * 256 + tid];
        Vs[tid] = V[nc * 256 + tid];
    }

    const __nv_bfloat16* gBh = g_Bhi;
    const __nv_bfloat16* gBl = g_Blo;

    float d[2][8][4];
#pragma unroll
    for (int mt = 0; mt < 2; ++mt)
#pragma unroll
        for (int nt = 0; nt < 8; ++nt)
#pragma unroll
            for (int e = 0; e < 4; ++e) d[mt][nt][e] = 0.f;

    float4 fr[2];

    // ---- prologue: chunk 0 -> stage 0 ----
    {
        const float* Fp = F + (size_t)m0 * ENC_;
#pragma unroll
        for (int j = 0; j < 2; ++j) {
            int v = tid + j * 512, row = v >> 3, q = v & 7;
            fr[j] = *(const float4*)(Fp + (size_t)row * ENC_ + q * 4);
        }
        const __nv_bfloat16* srcH = gBh + ((size_t)(nc * 256) << 5);
        const __nv_bfloat16* srcL = gBl + ((size_t)(nc * 256) << 5);
#pragma unroll
        for (int e = 0; e < 2; ++e) {
            int j = tid * 2 + e, row = j >> 2, q = j & 3;
            cp16(sb + OFF_BHI + row * PITCH + q * 16, srcH + (row << 5) + q * 8);
            cp16(sb + OFF_BLO + row * PITCH + q * 16, srcL + (row << 5) + q * 8);
        }
        cp_commit();
#pragma unroll
        for (int j = 0; j < 2; ++j) {
            int v = tid + j * 512, row = v >> 3, q = v & 7;
            float4 f = fr[j];
            __nv_bfloat162 h01 = __floats2bfloat162_rn(f.x, f.y);
            __nv_bfloat162 h23 = __floats2bfloat162_rn(f.z, f.w);
            __nv_bfloat162 l01 = __floats2bfloat162_rn(f.x - __low2float(h01),
                                                       f.y - __high2float(h01));
            __nv_bfloat162 l23 = __floats2bfloat162_rn(f.z - __low2float(h23),
                                                       f.w - __high2float(h23));
            uint32_t o = row * PITCH + q * 8;
            *(uint2*)(smem + OFF_AHI + o) = make_uint2(*(uint32_t*)&h01, *(uint32_t*)&h23);
            *(uint2*)(smem + OFF_ALO + o) = make_uint2(*(uint32_t*)&l01, *(uint32_t*)&l23);
        }
    }

    const uint32_t a_lrow = (uint32_t)(wm * 32 + (lane & 15));
    const uint32_t a_loff = (uint32_t)(((lane >> 4) & 1) * 16);
    const uint32_t b_lrow = (uint32_t)(wn * 64 + (lane & 7));
    const uint32_t b_loff = (uint32_t)(((lane >> 3) & 1) * 16);

#pragma unroll 1
    for (int i = 0; i < ENC_ / KC; ++i) {
        const int s = i & 1;
        const uint32_t stg = sb + s * STAGE;
        const uint32_t nstg = sb + (s ^ 1) * STAGE;

        // prefetch A(i+1) into regs (overlaps wait + compute)
        if (i + 1 < ENC_ / KC) {
            const float* Fp = F + (size_t)m0 * ENC_ + (i + 1) * KC;
#pragma unroll
            for (int j = 0; j < 2; ++j) {
                int v = tid + j * 512, row = v >> 3, q = v & 7;
                fr[j] = *(const float4*)(Fp + (size_t)row * ENC_ + q * 4);
            }
        }

        cp_wait0();
        __syncthreads();   // stage s fully populated; prev compute done with s^1

        if (i + 1 < ENC_ / KC) {
            const __nv_bfloat16* srcH = gBh + ((size_t)((i + 1) * 512 + nc * 256) << 5);
            const __nv_bfloat16* srcL = gBl + ((size_t)((i + 1) * 512 + nc * 256) << 5);
#pragma unroll
            for (int e = 0; e < 2; ++e) {
                int j = tid * 2 + e, row = j >> 2, q = j & 3;
                cp16(nstg + OFF_BHI + row * PITCH + q * 16, srcH + (row << 5) + q * 8);
                cp16(nstg + OFF_BLO + row * PITCH + q * 16, srcL + (row << 5) + q * 8);
            }
            cp_commit();
#pragma unroll
            for (int j = 0; j < 2; ++j) {
                int v = tid + j * 512, row = v >> 3, q = v & 7;
                float4 f = fr[j];
                __nv_bfloat162 h01 = __floats2bfloat162_rn(f.x, f.y);
                __nv_bfloat162 h23 = __floats2bfloat162_rn(f.z, f.w);
                __nv_bfloat162 l01 = __floats2bfloat162_rn(f.x - __low2float(h01),
                                                           f.y - __high2float(h01));
                __nv_bfloat162 l23 = __floats2bfloat162_rn(f.z - __low2float(h23),
                                                           f.w - __high2float(h23));
                uint32_t o = row * PITCH + q * 8;
                *(uint2*)((char*)smem + (s ^ 1) * STAGE + OFF_AHI + o) =
                    make_uint2(*(uint32_t*)&h01, *(uint32_t*)&h23);
                *(uint2*)((char*)smem + (s ^ 1) * STAGE + OFF_ALO + o) =
                    make_uint2(*(uint32_t*)&l01, *(uint32_t*)&l23);
            }
        }

        // ---- compute chunk i on stage s ----
#pragma unroll
        for (int kk = 0; kk < 2; ++kk) {
            const uint32_t ko = (uint32_t)(kk * 32);
            uint32_t ah0[4], ah1[4], al0[4], al1[4];
            ldsm_x4(ah0, stg + OFF_AHI + a_lrow * PITCH + a_loff + ko);
            ldsm_x4(ah1, stg + OFF_AHI + (a_lrow + 16) * PITCH + a_loff + ko);
            ldsm_x4(al0, stg + OFF_ALO + a_lrow * PITCH + a_loff + ko);
            ldsm_x4(al1, stg + OFF_ALO + (a_lrow + 16) * PITCH + a_loff + ko);
#pragma unroll
            for (int g = 0; g < 2; ++g) {          // B in groups of 4 nt (reg cap)
                uint32_t bh[4][2], bl[4][2];
#pragma unroll
                for (int t = 0; t < 4; ++t) {
                    int nt = g * 4 + t;
                    ldsm_x2(bh[t], stg + OFF_BHI + (b_lrow + nt * 8) * PITCH + b_loff + ko);
                    ldsm_x2(bl[t], stg + OFF_BLO + (b_lrow + nt * 8) * PITCH + b_loff + ko);
                }
#pragma unroll
                for (int t = 0; t < 4; ++t) {
                    int nt = g * 4 + t;
                    mma_bf16(d[0][nt], ah0, bh[t]);
                    mma_bf16(d[1][nt], ah1, bh[t]);
                    mma_bf16(d[0][nt], ah0, bl[t]);
                    mma_bf16(d[1][nt], ah1, bl[t]);
                    mma_bf16(d[0][nt], al0, bh[t]);
                    mma_bf16(d[1][nt], al1, bh[t]);
                }
            }
        }
    }

    // ---- epilogue: tanh + V-weighted row reduction over this 256-col half ----
#pragma unroll
    for (int mt = 0; mt < 2; ++mt) {
        float s0 = 0.f, s1 = 0.f;
#pragma unroll
        for (int nt = 0; nt < 8; ++nt) {
            int c0 = wn * 64 + nt * 8 + (lane & 3) * 2;
            float h0 = Hs[c0], v0 = Vs[c0];
            float h1 = Hs[c0 + 1], v1 = Vs[c0 + 1];
            s0 += fast_tanh(d[mt][nt][0] + h0) * v0 + fast_tanh(d[mt][nt][1] + h1) * v1;
            s1 += fast_tanh(d[mt][nt][2] + h0) * v0 + fast_tanh(d[mt][nt][3] + h1) * v1;
        }
#pragma unroll
        for (int o = 1; o <= 2; o <<= 1) {
            s0 += __shfl_xor_sync(~0u, s0, o);
            s1 += __shfl_xor_sync(~0u, s1, o);
        }
        if ((lane & 3) == 0) {
            int r = wm * 32 + mt * 16 + (lane >> 2);
            partS[wn * 128 + r]     = s0;
            partS[wn * 128 + r + 8] = s1;
        }
    }
    __syncthreads();
    if (tid < 128)
        g_scorep[nc * BL_ + m0 + tid] = partS[tid] + partS[128 + tid] +
                                        partS[256 + tid] + partS[384 + tid];
}

// ---------------------------------------------------------------------------
// Kernel D: combine partials + softmax over L per batch
// ---------------------------------------------------------------------------
__global__ void softmax_kernel(const float* __restrict__ bv, float* __restrict__ w) {
    __shared__ float redm[32];
    __shared__ float reds[32];
    const int b = blockIdx.x, t = threadIdx.x;
    const int idx = b * L_ + t;
    float s = g_scorep[idx] + g_scorep[BL_ + idx] + bv[0];
    float m = s;
#pragma unroll
    for (int o = 16; o > 0; o >>= 1) m = fmaxf(m, __shfl_xor_sync(~0u, m, o));
    if ((t & 31) == 0) redm[t >> 5] = m;
    __syncthreads();
    if (t < 32) {
        float v = redm[t];
#pragma unroll
        for (int o = 16; o > 0; o >>= 1) v = fmaxf(v, __shfl_xor_sync(~0u, v, o));
        redm[t] = v;
    }
    __syncthreads();
    m = redm[0];
    const float e = expf(s - m);
    float sum = e;
#pragma unroll
    for (int o = 16; o > 0; o >>= 1) sum += __shfl_xor_sync(~0u, sum, o);
    if ((t & 31) == 0) reds[t >> 5] = sum;
    __syncthreads();
    if (t < 32) {
        float v = reds[t];
#pragma unroll
        for (int o = 16; o > 0; o >>= 1) v += __shfl_xor_sync(~0u, v, o);
        reds[t] = v;
    }
    __syncthreads();
    w[idx] = e / reds[0];
}

// ---------------------------------------------------------------------------
// Kernel E/F: context = sum_l w*F  (L split in 8 partials, then reduced)
// ---------------------------------------------------------------------------
__global__ void context_part_kernel(const float* __restrict__ F,
                                    const float* __restrict__ w) {
    __shared__ float ws[128];
    const int b = blockIdx.y, z = blockIdx.z, t = threadIdx.x;
    const int l0 = z * 128;
    ws[t] = w[b * L_ + l0 + t];
    __syncthreads();
    const int e0 = blockIdx.x * 512 + t * 4;
    const float* fb = F + (size_t)b * L_ * ENC_ + (size_t)l0 * ENC_ + e0;
    float4 acc = make_float4(0.f, 0.f, 0.f, 0.f);
#pragma unroll 4
    for (int l = 0; l < 128; ++l) {
        float4 f = *(const float4*)(fb + (size_t)l * ENC_);
        const float wl = ws[l];
        acc.x += wl * f.x; acc.y += wl * f.y; acc.z += wl * f.z; acc.w += wl * f.w;
    }
    *(float4*)&g_ctxp[(size_t)(z * B_ + b) * ENC_ + e0] = acc;
}

__global__ void context_reduce_kernel(float* __restrict__ ctx) {
    const int i = (blockIdx.x * 256 + threadIdx.x) * 4;
    float4 acc = make_float4(0.f, 0.f, 0.f, 0.f);
#pragma unroll
    for (int p = 0; p < 8; ++p) {
        float4 a = *(const float4*)&g_ctxp[(size_t)p * B_ * ENC_ + i];
        acc.x += a.x; acc.y += a.y; acc.z += a.z; acc.w += a.w;
    }
    *(float4*)&ctx[i] = acc;
}

// ---------------------------------------------------------------------------
// Launch
// ---------------------------------------------------------------------------
extern "C" void kernel_launch(void* const* d_in, const int* in_sizes, int n_in,
                              void* d_out, int out_size) {
    const float* F   = (const float*)d_in[0];
    const float* hid = (const float*)d_in[1];
    const float* W1  = (const float*)d_in[2];
    const float* b1  = (const float*)d_in[3];
    const float* W2  = (const float*)d_in[4];
    const float* b2  = (const float*)d_in[5];
    const float* V   = (const float*)d_in[6];
    const float* bv  = (const float*)d_in[7];

    float* out = (float*)d_out;
    float* ctx = out;
    float* wts = out + B_ * ENC_;

    cudaFuncSetAttribute(score_mma_kernel,
                         cudaFuncAttributeMaxDynamicSharedMemorySize, SMEM_TOTAL);

    proj_h_kernel<<<B_, ATT_>>>(hid, W2, b2, b1);
    prep_B_kernel<<<(ENC_ * ATT_) / 256, 256>>>(W1);
    score_mma_kernel<<<dim3(2, BL_ / 128), 512, SMEM_TOTAL>>>(F, V);
    softmax_kernel<<<B_, L_>>>(bv, wts);
    context_part_kernel<<<dim3(ENC_ / 512, B_, 8), 128>>>(F, wts);
    context_reduce_kernel<<<(B_ * ENC_) / 1024, 256>>>(ctx);
}

// round 5
// speedup vs baseline: 1.0560x; 1.0560x over previous
#include <cuda_runtime.h>
#include <cuda_bf16.h>
#include <math.h>
#include <stdint.h>

#define B_   64
#define L_   1024
#define ENC_ 2048
#define DEC_ 512
#define ATT_ 512
#define BL_  (B_ * L_)

// ---------------------------------------------------------------------------
// Device scratch
// ---------------------------------------------------------------------------
__device__ float g_H[B_ * ATT_];                             // proj_h + b2 + b1
// W1 split bf16 hi/lo, layout [c=k/64][n 512][k 64]
__device__ __align__(128) __nv_bfloat16 g_Bhi[ENC_ * ATT_];
__device__ __align__(128) __nv_bfloat16 g_Blo[ENC_ * ATT_];
// F split bf16 hi/lo, layout [mb=row/128][c=k/64][row 128][k 64]
__device__ __align__(128) __nv_bfloat16 g_Fhi[(size_t)BL_ * ENC_];
__device__ __align__(128) __nv_bfloat16 g_Flo[(size_t)BL_ * ENC_];
__device__ float g_scorep[4 * BL_];                          // per-N-chunk score partials
__device__ float g_ctxp[8 * B_ * ENC_];                      // context partials

// ---------------------------------------------------------------------------
// Helpers
// ---------------------------------------------------------------------------
__device__ __forceinline__ uint32_t smem_u32(const void* p) {
    uint32_t a;
    asm("{ .reg .u64 t; cvta.to.shared.u64 t, %1; cvt.u32.u64 %0, t; }" : "=r"(a) : "l"(p));
    return a;
}
__device__ __forceinline__ void cp16(uint32_t dst, const void* src) {
    asm volatile("cp.async.cg.shared.global [%0], [%1], 16;" :: "r"(dst), "l"(src));
}
__device__ __forceinline__ void cp_commit() {
    asm volatile("cp.async.commit_group;" ::: "memory");
}
__device__ __forceinline__ void cp_wait0() {
    asm volatile("cp.async.wait_group 0;" ::: "memory");
}
__device__ __forceinline__ void ldsm_x4(uint32_t* r, uint32_t addr) {
    asm volatile("ldmatrix.sync.aligned.m8n8.x4.shared.b16 {%0,%1,%2,%3}, [%4];"
                 : "=r"(r[0]), "=r"(r[1]), "=r"(r[2]), "=r"(r[3]) : "r"(addr));
}
__device__ __forceinline__ void ldsm_x2(uint32_t* r, uint32_t addr) {
    asm volatile("ldmatrix.sync.aligned.m8n8.x2.shared.b16 {%0,%1}, [%2];"
                 : "=r"(r[0]), "=r"(r[1]) : "r"(addr));
}
__device__ __forceinline__ void mma_bf16(float* d, const uint32_t* a, const uint32_t* b) {
    asm volatile(
        "mma.sync.aligned.m16n8k16.row.col.f32.bf16.bf16.f32 "
        "{%0,%1,%2,%3}, {%4,%5,%6,%7}, {%8,%9}, {%0,%1,%2,%3};"
        : "+f"(d[0]), "+f"(d[1]), "+f"(d[2]), "+f"(d[3])
        : "r"(a[0]), "r"(a[1]), "r"(a[2]), "r"(a[3]), "r"(b[0]), "r"(b[1]));
}
__device__ __forceinline__ float fast_tanh(float x) {
    float e = __expf(2.f * x);
    return __fdividef(e - 1.f, e + 1.f);
}

// ---------------------------------------------------------------------------
// Kernel A: H = hidden @ W2 + b2 + b1
// ---------------------------------------------------------------------------
__global__ void proj_h_kernel(const float* __restrict__ hidden,
                              const float* __restrict__ W2,
                              const float* __restrict__ b2,
                              const float* __restrict__ b1) {
    __shared__ float hs[DEC_];
    int b = blockIdx.x, a = threadIdx.x;
    hs[a] = hidden[b * DEC_ + a];
    __syncthreads();
    float acc = 0.f;
#pragma unroll 8
    for (int d = 0; d < DEC_; ++d) acc += hs[d] * W2[d * ATT_ + a];
    g_H[b * ATT_ + a] = acc + b2[a] + b1[a];
}

// ---------------------------------------------------------------------------
// Kernel B1: split W1 [ENC, ATT] fp32 -> bf16 hi/lo, layout [c][n][k64]
// ---------------------------------------------------------------------------
__global__ void prep_B_kernel(const float* __restrict__ W1) {
    int idx = blockIdx.x * 256 + threadIdx.x;   // idx = k*512 + n
    if (idx >= ENC_ * ATT_) return;
    int k = idx >> 9, n = idx & 511;
    float x = W1[idx];
    __nv_bfloat16 h = __float2bfloat16(x);
    __nv_bfloat16 l = __float2bfloat16(x - __bfloat162float(h));
    int c = k >> 6, kk = k & 63;
    size_t o = ((size_t)(c * 512 + n) << 6) + kk;
    g_Bhi[o] = h;
    g_Blo[o] = l;
}

// ---------------------------------------------------------------------------
// Kernel B2: split F [BL, ENC] fp32 -> bf16 hi/lo, layout [mb][c][row][k64]
// ---------------------------------------------------------------------------
__global__ void prep_F_kernel(const float* __restrict__ F) {
    size_t f4 = (size_t)blockIdx.x * 256 + threadIdx.x;  // float4 index
    size_t r  = f4 >> 9;            // global row (ENC/4 = 512 float4 per row)
    int   c4  = (int)(f4 & 511);
    int   k   = c4 * 4;
    int   mb  = (int)(r >> 7), row = (int)(r & 127);
    int   c   = k >> 6, kk = k & 63;
    float4 f = *(const float4*)(F + (r << 11) + k);
    __nv_bfloat162 h01 = __floats2bfloat162_rn(f.x, f.y);
    __nv_bfloat162 h23 = __floats2bfloat162_rn(f.z, f.w);
    __nv_bfloat162 l01 = __floats2bfloat162_rn(f.x - __low2float(h01),
                                               f.y - __high2float(h01));
    __nv_bfloat162 l23 = __floats2bfloat162_rn(f.z - __low2float(h23),
                                               f.w - __high2float(h23));
    size_t o = (((size_t)(mb * 32 + c) * 128 + row) << 6) + kk;
    *(uint2*)(g_Fhi + o) = make_uint2(*(uint32_t*)&h01, *(uint32_t*)&h23);
    *(uint2*)(g_Flo + o) = make_uint2(*(uint32_t*)&l01, *(uint32_t*)&l23);
}

// ---------------------------------------------------------------------------
// Kernel C: fused bf16x3 mma.sync GEMM + tanh + V-reduction -> score partials
// Grid: (4 nc, 512 m)  [nc-major => L2 reuse of F tiles]
// CTA: 128x128 tile, 256 thr, KC=64, 2-stage cp.async pipeline, all-bf16 feeds.
// ---------------------------------------------------------------------------
static constexpr int KC     = 64;
static constexpr int PITCH  = 144;            // 128B data + 16B pad (bank-safe)
static constexpr int TILE   = 128 * PITCH;    // 18432
static constexpr int STAGE  = 4 * TILE;       // Ahi,Alo,Bhi,Blo = 73728
static constexpr int OFF_AHI = 0;
static constexpr int OFF_ALO = TILE;
static constexpr int OFF_BHI = 2 * TILE;
static constexpr int OFF_BLO = 3 * TILE;
static constexpr int OFF_PART = 2 * STAGE;            // 147456: 256 floats
static constexpr int OFF_H    = OFF_PART + 1024;      // 128 floats
static constexpr int OFF_V    = OFF_H + 512;          // 128 floats
static constexpr int SMEM_TOTAL = OFF_V + 512;        // 149504

__global__ __launch_bounds__(256, 1) void score_mma_kernel(const float* __restrict__ V)
{
    extern __shared__ char smem[];
    const uint32_t sb = smem_u32(smem);
    const int tid  = threadIdx.x;
    const int lane = tid & 31;
    const int wid  = tid >> 5;
    const int wm   = wid & 3;        // warp m: 4 x 32 rows
    const int wn   = wid >> 2;       // warp n: 2 x 64 cols
    const int nc   = blockIdx.x;     // n chunk (128 cols)
    const int mb   = blockIdx.y;
    const int m0   = mb * 128;
    const int b    = mb >> 3;

    float* partS = (float*)(smem + OFF_PART);
    float* Hs    = (float*)(smem + OFF_H);
    float* Vs    = (float*)(smem + OFF_V);
    if (tid < 128) {
        Hs[tid] = g_H[b * ATT_ + nc * 128 + tid];
        Vs[tid] = V[nc * 128 + tid];
    }

    float d[2][8][4];
#pragma unroll
    for (int mt = 0; mt < 2; ++mt)
#pragma unroll
        for (int nt = 0; nt < 8; ++nt)
#pragma unroll
            for (int e = 0; e < 4; ++e) d[mt][nt][e] = 0.f;

    // per-thread cp assignment: 4 per tile; j = tid + e*256; row=j>>3, q=j&7
    // A src chunk i: g_Fhi + ((mb*32 + i)*128 + row)*64 + q*8
    // B src chunk i: g_Bhi + ((i*512 + nc*128) + row)*64 + q*8

    // ---- prologue: chunk 0 -> stage 0 ----
#pragma unroll
    for (int e = 0; e < 4; ++e) {
        int j = tid + e * 256, row = j >> 3, q = j & 7;
        uint32_t dsto = (uint32_t)(row * PITCH + q * 16);
        size_t ao = (((size_t)(mb * 32 + 0) * 128 + row) << 6) + q * 8;
        size_t bo = (((size_t)(0 * 512 + nc * 128 + row)) << 6) + q * 8;
        cp16(sb + OFF_AHI + dsto, g_Fhi + ao);
        cp16(sb + OFF_ALO + dsto, g_Flo + ao);
        cp16(sb + OFF_BHI + dsto, g_Bhi + bo);
        cp16(sb + OFF_BLO + dsto, g_Blo + bo);
    }
    cp_commit();

    const uint32_t a_lrow = (uint32_t)(wm * 32 + (lane & 15));
    const uint32_t a_loff = (uint32_t)(((lane >> 4) & 1) * 16);
    const uint32_t b_lrow = (uint32_t)(wn * 64 + (lane & 7));
    const uint32_t b_loff = (uint32_t)(((lane >> 3) & 1) * 16);

#pragma unroll 1
    for (int i = 0; i < ENC_ / KC; ++i) {
        const int s = i & 1;
        const uint32_t stg  = sb + s * STAGE;
        const uint32_t nstg = sb + (s ^ 1) * STAGE;

        cp_wait0();
        __syncthreads();   // stage s populated; all warps done reading s^1

        if (i + 1 < ENC_ / KC) {
#pragma unroll
            for (int e = 0; e < 4; ++e) {
                int j = tid + e * 256, row = j >> 3, q = j & 7;
                uint32_t dsto = (uint32_t)(row * PITCH + q * 16);
                size_t ao = (((size_t)(mb * 32 + i + 1) * 128 + row) << 6) + q * 8;
                size_t bo = (((size_t)((i + 1) * 512 + nc * 128 + row)) << 6) + q * 8;
                cp16(nstg + OFF_AHI + dsto, g_Fhi + ao);
                cp16(nstg + OFF_ALO + dsto, g_Flo + ao);
                cp16(nstg + OFF_BHI + dsto, g_Bhi + bo);
                cp16(nstg + OFF_BLO + dsto, g_Blo + bo);
            }
            cp_commit();
        }

        // ---- compute chunk i on stage s: 4 k16 slabs ----
#pragma unroll
        for (int kk = 0; kk < 4; ++kk) {
            const uint32_t ko = (uint32_t)(kk * 32);
            uint32_t ah0[4], ah1[4], al0[4], al1[4];
            ldsm_x4(ah0, stg + OFF_AHI + a_lrow * PITCH + a_loff + ko);
            ldsm_x4(ah1, stg + OFF_AHI + (a_lrow + 16) * PITCH + a_loff + ko);
            ldsm_x4(al0, stg + OFF_ALO + a_lrow * PITCH + a_loff + ko);
            ldsm_x4(al1, stg + OFF_ALO + (a_lrow + 16) * PITCH + a_loff + ko);
            uint32_t bh[8][2], bl[8][2];
#pragma unroll
            for (int nt = 0; nt < 8; ++nt) {
                ldsm_x2(bh[nt], stg + OFF_BHI + (b_lrow + nt * 8) * PITCH + b_loff + ko);
                ldsm_x2(bl[nt], stg + OFF_BLO + (b_lrow + nt * 8) * PITCH + b_loff + ko);
            }
#pragma unroll
            for (int nt = 0; nt < 8; ++nt) {
                mma_bf16(d[0][nt], ah0, bh[nt]);
                mma_bf16(d[1][nt], ah1, bh[nt]);
                mma_bf16(d[0][nt], ah0, bl[nt]);
                mma_bf16(d[1][nt], ah1, bl[nt]);
                mma_bf16(d[0][nt], al0, bh[nt]);
                mma_bf16(d[1][nt], al1, bh[nt]);
            }
        }
    }

    // ---- epilogue: tanh + V-weighted row reduction over this 128-col chunk ----
#pragma unroll
    for (int mt = 0; mt < 2; ++mt) {
        float s0 = 0.f, s1 = 0.f;
#pragma unroll
        for (int nt = 0; nt < 8; ++nt) {
            int c0 = wn * 64 + nt * 8 + (lane & 3) * 2;
            float h0 = Hs[c0], v0 = Vs[c0];
            float h1 = Hs[c0 + 1], v1 = Vs[c0 + 1];
            s0 += fast_tanh(d[mt][nt][0] + h0) * v0 + fast_tanh(d[mt][nt][1] + h1) * v1;
            s1 += fast_tanh(d[mt][nt][2] + h0) * v0 + fast_tanh(d[mt][nt][3] + h1) * v1;
        }
#pragma unroll
        for (int o = 1; o <= 2; o <<= 1) {
            s0 += __shfl_xor_sync(~0u, s0, o);
            s1 += __shfl_xor_sync(~0u, s1, o);
        }
        if ((lane & 3) == 0) {
            int r = wm * 32 + mt * 16 + (lane >> 2);
            partS[wn * 128 + r]     = s0;
            partS[wn * 128 + r + 8] = s1;
        }
    }
    __syncthreads();
    if (tid < 128)
        g_scorep[nc * BL_ + m0 + tid] = partS[tid] + partS[128 + tid];
}

// ---------------------------------------------------------------------------
// Kernel D: combine partials + softmax over L per batch
// ---------------------------------------------------------------------------
__global__ void softmax_kernel(const float* __restrict__ bv, float* __restrict__ w) {
    __shared__ float redm[32];
    __shared__ float reds[32];
    const int b = blockIdx.x, t = threadIdx.x;
    const int idx = b * L_ + t;
    float s = g_scorep[idx] + g_scorep[BL_ + idx] + g_scorep[2 * BL_ + idx] +
              g_scorep[3 * BL_ + idx] + bv[0];
    float m = s;
#pragma unroll
    for (int o = 16; o > 0; o >>= 1) m = fmaxf(m, __shfl_xor_sync(~0u, m, o));
    if ((t & 31) == 0) redm[t >> 5] = m;
    __syncthreads();
    if (t < 32) {
        float v = redm[t];
#pragma unroll
        for (int o = 16; o > 0; o >>= 1) v = fmaxf(v, __shfl_xor_sync(~0u, v, o));
        redm[t] = v;
    }
    __syncthreads();
    m = redm[0];
    const float e = expf(s - m);
    float sum = e;
#pragma unroll
    for (int o = 16; o > 0; o >>= 1) sum += __shfl_xor_sync(~0u, sum, o);
    if ((t & 31) == 0) reds[t >> 5] = sum;
    __syncthreads();
    if (t < 32) {
        float v = reds[t];
#pragma unroll
        for (int o = 16; o > 0; o >>= 1) v += __shfl_xor_sync(~0u, v, o);
        reds[t] = v;
    }
    __syncthreads();
    w[idx] = e / reds[0];
}

// ---------------------------------------------------------------------------
// Kernel E/F: context = sum_l w*F  (L split in 8 partials, then reduced)
// ---------------------------------------------------------------------------
__global__ void context_part_kernel(const float* __restrict__ F,
                                    const float* __restrict__ w) {
    __shared__ float ws[128];
    const int b = blockIdx.y, z = blockIdx.z, t = threadIdx.x;
    const int l0 = z * 128;
    ws[t] = w[b * L_ + l0 + t];
    __syncthreads();
    const int e0 = blockIdx.x * 512 + t * 4;
    const float* fb = F + (size_t)b * L_ * ENC_ + (size_t)l0 * ENC_ + e0;
    float4 acc = make_float4(0.f, 0.f, 0.f, 0.f);
#pragma unroll 4
    for (int l = 0; l < 128; ++l) {
        float4 f = *(const float4*)(fb + (size_t)l * ENC_);
        const float wl = ws[l];
        acc.x += wl * f.x; acc.y += wl * f.y; acc.z += wl * f.z; acc.w += wl * f.w;
    }
    *(float4*)&g_ctxp[(size_t)(z * B_ + b) * ENC_ + e0] = acc;
}

__global__ void context_reduce_kernel(float* __restrict__ ctx) {
    const int i = (blockIdx.x * 256 + threadIdx.x) * 4;
    float4 acc = make_float4(0.f, 0.f, 0.f, 0.f);
#pragma unroll
    for (int p = 0; p < 8; ++p) {
        float4 a = *(const float4*)&g_ctxp[(size_t)p * B_ * ENC_ + i];
        acc.x += a.x; acc.y += a.y; acc.z += a.z; acc.w += a.w;
    }
    *(float4*)&ctx[i] = acc;
}

// ---------------------------------------------------------------------------
// Launch
// ---------------------------------------------------------------------------
extern "C" void kernel_launch(void* const* d_in, const int* in_sizes, int n_in,
                              void* d_out, int out_size) {
    const float* F   = (const float*)d_in[0];
    const float* hid = (const float*)d_in[1];
    const float* W1  = (const float*)d_in[2];
    const float* b1  = (const float*)d_in[3];
    const float* W2  = (const float*)d_in[4];
    const float* b2  = (const float*)d_in[5];
    const float* V   = (const float*)d_in[6];
    const float* bv  = (const float*)d_in[7];

    float* out = (float*)d_out;
    float* ctx = out;
    float* wts = out + B_ * ENC_;

    cudaFuncSetAttribute(score_mma_kernel,
                         cudaFuncAttributeMaxDynamicSharedMemorySize, SMEM_TOTAL);

    proj_h_kernel<<<B_, ATT_>>>(hid, W2, b2, b1);
    prep_B_kernel<<<(ENC_ * ATT_) / 256, 256>>>(W1);
    prep_F_kernel<<<(int)(((size_t)BL_ * ENC_ / 4) / 256), 256>>>(F);
    score_mma_kernel<<<dim3(4, BL_ / 128), 256, SMEM_TOTAL>>>(V);
    softmax_kernel<<<B_, L_>>>(bv, wts);
    context_part_kernel<<<dim3(ENC_ / 512, B_, 8), 128>>>(F, wts);
    context_reduce_kernel<<<(B_ * ENC_) / 1024, 256>>>(ctx);
}

// round 6
// speedup vs baseline: 1.1302x; 1.0703x over previous
#include <cuda_runtime.h>
#include <cuda_bf16.h>
#include <math.h>
#include <stdint.h>

#define B_   64
#define L_   1024
#define ENC_ 2048
#define DEC_ 512
#define ATT_ 512
#define BL_  (B_ * L_)

// ---------------------------------------------------------------------------
// Device scratch
// ---------------------------------------------------------------------------
__device__ float g_H[B_ * ATT_];                             // proj_h + b2 + b1
// W1 split bf16 hi/lo, layout [c=k/32][n 512][k 32]
__device__ __align__(128) __nv_bfloat16 g_Bhi[ENC_ * ATT_];
__device__ __align__(128) __nv_bfloat16 g_Blo[ENC_ * ATT_];
// F split bf16 hi/lo, layout [mb=row/128][c=k/32][row 128][k 32]
__device__ __align__(128) __nv_bfloat16 g_Fhi[(size_t)BL_ * ENC_];
__device__ __align__(128) __nv_bfloat16 g_Flo[(size_t)BL_ * ENC_];
__device__ float g_scorep[4 * BL_];                          // per-N-chunk score partials
__device__ float g_ctxp[8 * B_ * ENC_];                      // context partials

// ---------------------------------------------------------------------------
// Helpers
// ---------------------------------------------------------------------------
__device__ __forceinline__ uint32_t smem_u32(const void* p) {
    uint32_t a;
    asm("{ .reg .u64 t; cvta.to.shared.u64 t, %1; cvt.u32.u64 %0, t; }" : "=r"(a) : "l"(p));
    return a;
}
__device__ __forceinline__ void cp16(uint32_t dst, const void* src) {
    asm volatile("cp.async.cg.shared.global [%0], [%1], 16;" :: "r"(dst), "l"(src));
}
__device__ __forceinline__ void cp_commit() {
    asm volatile("cp.async.commit_group;" ::: "memory");
}
__device__ __forceinline__ void cp_wait0() {
    asm volatile("cp.async.wait_group 0;" ::: "memory");
}
__device__ __forceinline__ void ldsm_x4(uint32_t* r, uint32_t addr) {
    asm volatile("ldmatrix.sync.aligned.m8n8.x4.shared.b16 {%0,%1,%2,%3}, [%4];"
                 : "=r"(r[0]), "=r"(r[1]), "=r"(r[2]), "=r"(r[3]) : "r"(addr));
}
__device__ __forceinline__ void ldsm_x2(uint32_t* r, uint32_t addr) {
    asm volatile("ldmatrix.sync.aligned.m8n8.x2.shared.b16 {%0,%1}, [%2];"
                 : "=r"(r[0]), "=r"(r[1]) : "r"(addr));
}
__device__ __forceinline__ void mma_bf16(float* d, const uint32_t* a, const uint32_t* b) {
    asm volatile(
        "mma.sync.aligned.m16n8k16.row.col.f32.bf16.bf16.f32 "
        "{%0,%1,%2,%3}, {%4,%5,%6,%7}, {%8,%9}, {%0,%1,%2,%3};"
        : "+f"(d[0]), "+f"(d[1]), "+f"(d[2]), "+f"(d[3])
        : "r"(a[0]), "r"(a[1]), "r"(a[2]), "r"(a[3]), "r"(b[0]), "r"(b[1]));
}
__device__ __forceinline__ float fast_tanh(float x) {
    float e = __expf(2.f * x);
    return __fdividef(e - 1.f, e + 1.f);
}

// ---------------------------------------------------------------------------
// Kernel A: H = hidden @ W2 + b2 + b1
// ---------------------------------------------------------------------------
__global__ void proj_h_kernel(const float* __restrict__ hidden,
                              const float* __restrict__ W2,
                              const float* __restrict__ b2,
                              const float* __restrict__ b1) {
    __shared__ float hs[DEC_];
    int b = blockIdx.x, a = threadIdx.x;
    hs[a] = hidden[b * DEC_ + a];
    __syncthreads();
    float acc = 0.f;
#pragma unroll 8
    for (int d = 0; d < DEC_; ++d) acc += hs[d] * W2[d * ATT_ + a];
    g_H[b * ATT_ + a] = acc + b2[a] + b1[a];
}

// ---------------------------------------------------------------------------
// Kernel B1: split W1 [ENC, ATT] fp32 -> bf16 hi/lo, layout [c][n][k32]
// ---------------------------------------------------------------------------
__global__ void prep_B_kernel(const float* __restrict__ W1) {
    int idx = blockIdx.x * 256 + threadIdx.x;   // idx = k*512 + n
    if (idx >= ENC_ * ATT_) return;
    int k = idx >> 9, n = idx & 511;
    float x = W1[idx];
    __nv_bfloat16 h = __float2bfloat16(x);
    __nv_bfloat16 l = __float2bfloat16(x - __bfloat162float(h));
    int c = k >> 5, kk = k & 31;
    size_t o = ((size_t)(c * 512 + n) << 5) + kk;
    g_Bhi[o] = h;
    g_Blo[o] = l;
}

// ---------------------------------------------------------------------------
// Kernel B2: split F [BL, ENC] fp32 -> bf16 hi/lo, layout [mb][c][row][k32]
// ---------------------------------------------------------------------------
__global__ void prep_F_kernel(const float* __restrict__ F) {
    size_t f4 = (size_t)blockIdx.x * 256 + threadIdx.x;  // float4 index
    size_t r  = f4 >> 9;            // global row (512 float4 per row)
    int   k   = (int)(f4 & 511) * 4;
    int   mb  = (int)(r >> 7), row = (int)(r & 127);
    int   c   = k >> 5, kk = k & 31;
    float4 f = *(const float4*)(F + (r << 11) + k);
    __nv_bfloat162 h01 = __floats2bfloat162_rn(f.x, f.y);
    __nv_bfloat162 h23 = __floats2bfloat162_rn(f.z, f.w);
    __nv_bfloat162 l01 = __floats2bfloat162_rn(f.x - __low2float(h01),
                                               f.y - __high2float(h01));
    __nv_bfloat162 l23 = __floats2bfloat162_rn(f.z - __low2float(h23),
                                               f.w - __high2float(h23));
    size_t o = (((size_t)(mb * 64 + c) * 128 + row) << 5) + kk;
    *(uint2*)(g_Fhi + o) = make_uint2(*(uint32_t*)&h01, *(uint32_t*)&h23);
    *(uint2*)(g_Flo + o) = make_uint2(*(uint32_t*)&l01, *(uint32_t*)&l23);
}

// ---------------------------------------------------------------------------
// Kernel C: fused bf16x3 mma.sync GEMM + tanh + V-reduction -> score partials
// Grid: (4 nc, 512 m)  [nc-major => L2 reuse of F tiles]
// CTA: 128x128 tile, 256 thr, KC=32, 2-stage cp.async, 2 CTAs/SM (regs<=128).
// ---------------------------------------------------------------------------
static constexpr int PITCH  = 80;             // 64B data + 16B pad
static constexpr int TILE   = 128 * PITCH;    // 10240
static constexpr int STAGE  = 4 * TILE;       // Ahi,Alo,Bhi,Blo = 40960
static constexpr int OFF_AHI = 0;
static constexpr int OFF_ALO = TILE;
static constexpr int OFF_BHI = 2 * TILE;
static constexpr int OFF_BLO = 3 * TILE;
static constexpr int OFF_PART = 2 * STAGE;            // 81920: 256 floats
static constexpr int OFF_H    = OFF_PART + 1024;      // 128 floats
static constexpr int OFF_V    = OFF_H + 512;          // 128 floats
static constexpr int SMEM_TOTAL = OFF_V + 512;        // 84480

__global__ __launch_bounds__(256, 2) void score_mma_kernel(const float* __restrict__ V)
{
    extern __shared__ char smem[];
    const uint32_t sb = smem_u32(smem);
    const int tid  = threadIdx.x;
    const int lane = tid & 31;
    const int wid  = tid >> 5;
    const int wm   = wid & 3;        // warp m: 4 x 32 rows
    const int wn   = wid >> 2;       // warp n: 2 x 64 cols
    const int nc   = blockIdx.x;     // n chunk (128 cols)
    const int mb   = blockIdx.y;
    const int m0   = mb * 128;
    const int b    = mb >> 3;

    float* partS = (float*)(smem + OFF_PART);
    float* Hs    = (float*)(smem + OFF_H);
    float* Vs    = (float*)(smem + OFF_V);
    if (tid < 128) {
        Hs[tid] = g_H[b * ATT_ + nc * 128 + tid];
        Vs[tid] = V[nc * 128 + tid];
    }

    float d[2][8][4];
#pragma unroll
    for (int mt = 0; mt < 2; ++mt)
#pragma unroll
        for (int nt = 0; nt < 8; ++nt)
#pragma unroll
            for (int e = 0; e < 4; ++e) d[mt][nt][e] = 0.f;

    // per-thread cp: per tile 512 x 16B units -> 2/thread: j=tid+e*256, row=j>>2, q=j&3
    // A src chunk i: g_Fhi + ((mb*64 + i)*128 + row)*32 + q*8
    // B src chunk i: g_Bhi + ((i*512 + nc*128 + row))*32 + q*8

    // ---- prologue: chunk 0 -> stage 0 ----
#pragma unroll
    for (int e = 0; e < 2; ++e) {
        int j = tid + e * 256, row = j >> 2, q = j & 3;
        uint32_t dsto = (uint32_t)(row * PITCH + q * 16);
        size_t ao = (((size_t)(mb * 64 + 0) * 128 + row) << 5) + q * 8;
        size_t bo = (((size_t)(0 * 512 + nc * 128 + row)) << 5) + q * 8;
        cp16(sb + OFF_AHI + dsto, g_Fhi + ao);
        cp16(sb + OFF_ALO + dsto, g_Flo + ao);
        cp16(sb + OFF_BHI + dsto, g_Bhi + bo);
        cp16(sb + OFF_BLO + dsto, g_Blo + bo);
    }
    cp_commit();

    const uint32_t a_lrow = (uint32_t)(wm * 32 + (lane & 15));
    const uint32_t a_loff = (uint32_t)(((lane >> 4) & 1) * 16);
    const uint32_t b_lrow = (uint32_t)(wn * 64 + (lane & 7));
    const uint32_t b_loff = (uint32_t)(((lane >> 3) & 1) * 16);

#pragma unroll 1
    for (int i = 0; i < ENC_ / 32; ++i) {
        const int s = i & 1;
        const uint32_t stg  = sb + s * STAGE;
        const uint32_t nstg = sb + (s ^ 1) * STAGE;

        cp_wait0();
        __syncthreads();   // stage s populated; all warps done reading s^1

        if (i + 1 < ENC_ / 32) {
#pragma unroll
            for (int e = 0; e < 2; ++e) {
                int j = tid + e * 256, row = j >> 2, q = j & 3;
                uint32_t dsto = (uint32_t)(row * PITCH + q * 16);
                size_t ao = (((size_t)(mb * 64 + i + 1) * 128 + row) << 5) + q * 8;
                size_t bo = (((size_t)((i + 1) * 512 + nc * 128 + row)) << 5) + q * 8;
                cp16(nstg + OFF_AHI + dsto, g_Fhi + ao);
                cp16(nstg + OFF_ALO + dsto, g_Flo + ao);
                cp16(nstg + OFF_BHI + dsto, g_Bhi + bo);
                cp16(nstg + OFF_BLO + dsto, g_Blo + bo);
            }
            cp_commit();
        }

        // ---- compute chunk i on stage s: 2 k16 slabs ----
#pragma unroll
        for (int kk = 0; kk < 2; ++kk) {
            const uint32_t ko = (uint32_t)(kk * 32);
            uint32_t ah0[4], ah1[4], al0[4], al1[4];
            ldsm_x4(ah0, stg + OFF_AHI + a_lrow * PITCH + a_loff + ko);
            ldsm_x4(ah1, stg + OFF_AHI + (a_lrow + 16) * PITCH + a_loff + ko);
            ldsm_x4(al0, stg + OFF_ALO + a_lrow * PITCH + a_loff + ko);
            ldsm_x4(al1, stg + OFF_ALO + (a_lrow + 16) * PITCH + a_loff + ko);
#pragma unroll
            for (int g = 0; g < 2; ++g) {          // B in groups of 4 (reg cap)
                uint32_t bh[4][2], bl[4][2];
#pragma unroll
                for (int t = 0; t < 4; ++t) {
                    int nt = g * 4 + t;
                    ldsm_x2(bh[t], stg + OFF_BHI + (b_lrow + nt * 8) * PITCH + b_loff + ko);
                    ldsm_x2(bl[t], stg + OFF_BLO + (b_lrow + nt * 8) * PITCH + b_loff + ko);
                }
#pragma unroll
                for (int t = 0; t < 4; ++t) {
                    int nt = g * 4 + t;
                    mma_bf16(d[0][nt], ah0, bh[t]);
                    mma_bf16(d[1][nt], ah1, bh[t]);
                    mma_bf16(d[0][nt], ah0, bl[t]);
                    mma_bf16(d[1][nt], ah1, bl[t]);
                    mma_bf16(d[0][nt], al0, bh[t]);
                    mma_bf16(d[1][nt], al1, bh[t]);
                }
            }
        }
    }

    // ---- epilogue: tanh + V-weighted row reduction over this 128-col chunk ----
#pragma unroll
    for (int mt = 0; mt < 2; ++mt) {
        float s0 = 0.f, s1 = 0.f;
#pragma unroll
        for (int nt = 0; nt < 8; ++nt) {
            int c0 = wn * 64 + nt * 8 + (lane & 3) * 2;
            float h0 = Hs[c0], v0 = Vs[c0];
            float h1 = Hs[c0 + 1], v1 = Vs[c0 + 1];
            s0 += fast_tanh(d[mt][nt][0] + h0) * v0 + fast_tanh(d[mt][nt][1] + h1) * v1;
            s1 += fast_tanh(d[mt][nt][2] + h0) * v0 + fast_tanh(d[mt][nt][3] + h1) * v1;
        }
#pragma unroll
        for (int o = 1; o <= 2; o <<= 1) {
            s0 += __shfl_xor_sync(~0u, s0, o);
            s1 += __shfl_xor_sync(~0u, s1, o);
        }
        if ((lane & 3) == 0) {
            int r = wm * 32 + mt * 16 + (lane >> 2);
            partS[wn * 128 + r]     = s0;
            partS[wn * 128 + r + 8] = s1;
        }
    }
    __syncthreads();
    if (tid < 128)
        g_scorep[nc * BL_ + m0 + tid] = partS[tid] + partS[128 + tid];
}

// ---------------------------------------------------------------------------
// Kernel D: combine partials + softmax over L per batch
// ---------------------------------------------------------------------------
__global__ void softmax_kernel(const float* __restrict__ bv, float* __restrict__ w) {
    __shared__ float redm[32];
    __shared__ float reds[32];
    const int b = blockIdx.x, t = threadIdx.x;
    const int idx = b * L_ + t;
    float s = g_scorep[idx] + g_scorep[BL_ + idx] + g_scorep[2 * BL_ + idx] +
              g_scorep[3 * BL_ + idx] + bv[0];
    float m = s;
#pragma unroll
    for (int o = 16; o > 0; o >>= 1) m = fmaxf(m, __shfl_xor_sync(~0u, m, o));
    if ((t & 31) == 0) redm[t >> 5] = m;
    __syncthreads();
    if (t < 32) {
        float v = redm[t];
#pragma unroll
        for (int o = 16; o > 0; o >>= 1) v = fmaxf(v, __shfl_xor_sync(~0u, v, o));
        redm[t] = v;
    }
    __syncthreads();
    m = redm[0];
    const float e = expf(s - m);
    float sum = e;
#pragma unroll
    for (int o = 16; o > 0; o >>= 1) sum += __shfl_xor_sync(~0u, sum, o);
    if ((t & 31) == 0) reds[t >> 5] = sum;
    __syncthreads();
    if (t < 32) {
        float v = reds[t];
#pragma unroll
        for (int o = 16; o > 0; o >>= 1) v += __shfl_xor_sync(~0u, v, o);
        reds[t] = v;
    }
    __syncthreads();
    w[idx] = e / reds[0];
}

// ---------------------------------------------------------------------------
// Kernel E/F: context = sum_l w*F  (L split in 8 partials, then reduced)
// ---------------------------------------------------------------------------
__global__ void context_part_kernel(const float* __restrict__ F,
                                    const float* __restrict__ w) {
    __shared__ float ws[128];
    const int b = blockIdx.y, z = blockIdx.z, t = threadIdx.x;
    const int l0 = z * 128;
    ws[t] = w[b * L_ + l0 + t];
    __syncthreads();
    const int e0 = blockIdx.x * 512 + t * 4;
    const float* fb = F + (size_t)b * L_ * ENC_ + (size_t)l0 * ENC_ + e0;
    float4 acc = make_float4(0.f, 0.f, 0.f, 0.f);
#pragma unroll 4
    for (int l = 0; l < 128; ++l) {
        float4 f = *(const float4*)(fb + (size_t)l * ENC_);
        const float wl = ws[l];
        acc.x += wl * f.x; acc.y += wl * f.y; acc.z += wl * f.z; acc.w += wl * f.w;
    }
    *(float4*)&g_ctxp[(size_t)(z * B_ + b) * ENC_ + e0] = acc;
}

__global__ void context_reduce_kernel(float* __restrict__ ctx) {
    const int i = (blockIdx.x * 256 + threadIdx.x) * 4;
    float4 acc = make_float4(0.f, 0.f, 0.f, 0.f);
#pragma unroll
    for (int p = 0; p < 8; ++p) {
        float4 a = *(const float4*)&g_ctxp[(size_t)p * B_ * ENC_ + i];
        acc.x += a.x; acc.y += a.y; acc.z += a.z; acc.w += a.w;
    }
    *(float4*)&ctx[i] = acc;
}

// ---------------------------------------------------------------------------
// Launch
// ---------------------------------------------------------------------------
extern "C" void kernel_launch(void* const* d_in, const int* in_sizes, int n_in,
                              void* d_out, int out_size) {
    const float* F   = (const float*)d_in[0];
    const float* hid = (const float*)d_in[1];
    const float* W1  = (const float*)d_in[2];
    const float* b1  = (const float*)d_in[3];
    const float* W2  = (const float*)d_in[4];
    const float* b2  = (const float*)d_in[5];
    const float* V   = (const float*)d_in[6];
    const float* bv  = (const float*)d_in[7];

    float* out = (float*)d_out;
    float* ctx = out;
    float* wts = out + B_ * ENC_;

    cudaFuncSetAttribute(score_mma_kernel,
                         cudaFuncAttributeMaxDynamicSharedMemorySize, SMEM_TOTAL);

    proj_h_kernel<<<B_, ATT_>>>(hid, W2, b2, b1);
    prep_B_kernel<<<(ENC_ * ATT_) / 256, 256>>>(W1);
    prep_F_kernel<<<(int)(((size_t)BL_ * ENC_ / 4) / 256), 256>>>(F);
    score_mma_kernel<<<dim3(4, BL_ / 128), 256, SMEM_TOTAL>>>(V);
    softmax_kernel<<<B_, L_>>>(bv, wts);
    context_part_kernel<<<dim3(ENC_ / 512, B_, 8), 128>>>(F, wts);
    context_reduce_kernel<<<(B_ * ENC_) / 1024, 256>>>(ctx);
}

// round 7
// speedup vs baseline: 2.3020x; 2.0368x over previous
#include <cuda_runtime.h>
#include <cuda_fp16.h>
#include <math.h>
#include <stdint.h>

#define B_   64
#define L_   1024
#define ENC_ 2048
#define DEC_ 512
#define ATT_ 512
#define BL_  (B_ * L_)

// ---------------------------------------------------------------------------
// Device scratch
// ---------------------------------------------------------------------------
__device__ float g_H[B_ * ATT_];                          // proj_h + b2 + b1
// W1 fp16, layout [c=k/64][n 512][k 64]
__device__ __align__(128) __half g_B16[ENC_ * ATT_];
// F fp16, layout [mb=row/128][c=k/64][row 128][k 64]
__device__ __align__(128) __half g_F16[(size_t)BL_ * ENC_];
__device__ float g_scorep[4 * BL_];                       // per-N-chunk score partials
__device__ float g_ctxp[8 * B_ * ENC_];                   // context partials

// ---------------------------------------------------------------------------
// Helpers
// ---------------------------------------------------------------------------
__device__ __forceinline__ uint32_t smem_u32(const void* p) {
    uint32_t a;
    asm("{ .reg .u64 t; cvta.to.shared.u64 t, %1; cvt.u32.u64 %0, t; }" : "=r"(a) : "l"(p));
    return a;
}
__device__ __forceinline__ void cp16(uint32_t dst, const void* src) {
    asm volatile("cp.async.cg.shared.global [%0], [%1], 16;" :: "r"(dst), "l"(src));
}
__device__ __forceinline__ void cp_commit() {
    asm volatile("cp.async.commit_group;" ::: "memory");
}
__device__ __forceinline__ void cp_wait0() {
    asm volatile("cp.async.wait_group 0;" ::: "memory");
}
__device__ __forceinline__ void ldsm_x4(uint32_t* r, uint32_t addr) {
    asm volatile("ldmatrix.sync.aligned.m8n8.x4.shared.b16 {%0,%1,%2,%3}, [%4];"
                 : "=r"(r[0]), "=r"(r[1]), "=r"(r[2]), "=r"(r[3]) : "r"(addr));
}
__device__ __forceinline__ void mma_f16(float* d, const uint32_t* a, const uint32_t* b) {
    asm volatile(
        "mma.sync.aligned.m16n8k16.row.col.f32.f16.f16.f32 "
        "{%0,%1,%2,%3}, {%4,%5,%6,%7}, {%8,%9}, {%0,%1,%2,%3};"
        : "+f"(d[0]), "+f"(d[1]), "+f"(d[2]), "+f"(d[3])
        : "r"(a[0]), "r"(a[1]), "r"(a[2]), "r"(a[3]), "r"(b[0]), "r"(b[1]));
}
__device__ __forceinline__ float fast_tanh(float x) {
    float e = __expf(2.f * x);
    return __fdividef(e - 1.f, e + 1.f);
}

// ---------------------------------------------------------------------------
// Kernel A: H = hidden @ W2 + b2 + b1
// ---------------------------------------------------------------------------
__global__ void proj_h_kernel(const float* __restrict__ hidden,
                              const float* __restrict__ W2,
                              const float* __restrict__ b2,
                              const float* __restrict__ b1) {
    __shared__ float hs[DEC_];
    int b = blockIdx.x, a = threadIdx.x;
    hs[a] = hidden[b * DEC_ + a];
    __syncthreads();
    float acc = 0.f;
#pragma unroll 8
    for (int d = 0; d < DEC_; ++d) acc += hs[d] * W2[d * ATT_ + a];
    g_H[b * ATT_ + a] = acc + b2[a] + b1[a];
}

// ---------------------------------------------------------------------------
// Kernel B1: W1 [ENC, ATT] fp32 -> fp16, layout [c][n][k64]
// ---------------------------------------------------------------------------
__global__ void prep_B_kernel(const float* __restrict__ W1) {
    int idx = blockIdx.x * 256 + threadIdx.x;   // idx = k*512 + n
    if (idx >= ENC_ * ATT_) return;
    int k = idx >> 9, n = idx & 511;
    int c = k >> 6, kk = k & 63;
    g_B16[((size_t)(c * 512 + n) << 6) + kk] = __float2half_rn(W1[idx]);
}

// ---------------------------------------------------------------------------
// Kernel B2: F [BL, ENC] fp32 -> fp16, layout [mb][c][row][k64]
// ---------------------------------------------------------------------------
__global__ void prep_F_kernel(const float* __restrict__ F) {
    size_t f4 = (size_t)blockIdx.x * 256 + threadIdx.x;  // float4 index
    size_t r  = f4 >> 9;            // global row (512 float4 per row)
    int   k   = (int)(f4 & 511) * 4;
    int   mb  = (int)(r >> 7), row = (int)(r & 127);
    int   c   = k >> 6, kk = k & 63;
    float4 f = *(const float4*)(F + (r << 11) + k);
    __half2 h01 = __floats2half2_rn(f.x, f.y);
    __half2 h23 = __floats2half2_rn(f.z, f.w);
    size_t o = (((size_t)(mb * 32 + c) * 128 + row) << 6) + kk;
    *(uint2*)(g_F16 + o) = make_uint2(*(uint32_t*)&h01, *(uint32_t*)&h23);
}

// ---------------------------------------------------------------------------
// Kernel C: fused fp16 mma.sync GEMM + tanh + V-reduction -> score partials
// Grid: (4 nc, 512 m)  [nc-major => L2 reuse of F tiles]
// CTA: 128x128 tile, 256 thr, KC=64, 2-stage cp.async, 2 CTAs/SM.
// ---------------------------------------------------------------------------
static constexpr int PITCH  = 144;            // 128B data + 16B pad
static constexpr int TILE   = 128 * PITCH;    // 18432
static constexpr int STAGE  = 2 * TILE;       // A,B = 36864
static constexpr int OFF_A  = 0;
static constexpr int OFF_B  = TILE;
static constexpr int OFF_PART = 2 * STAGE;            // 73728: 256 floats
static constexpr int OFF_H    = OFF_PART + 1024;
static constexpr int OFF_V    = OFF_H + 512;
static constexpr int SMEM_TOTAL = OFF_V + 512;        // 75776

__global__ __launch_bounds__(256, 2) void score_mma_kernel(const float* __restrict__ V)
{
    extern __shared__ char smem[];
    const uint32_t sb = smem_u32(smem);
    const int tid  = threadIdx.x;
    const int lane = tid & 31;
    const int wid  = tid >> 5;
    const int wm   = wid & 3;        // warp m: 4 x 32 rows
    const int wn   = wid >> 2;       // warp n: 2 x 64 cols
    const int nc   = blockIdx.x;     // n chunk (128 cols)
    const int mb   = blockIdx.y;
    const int m0   = mb * 128;
    const int b    = mb >> 3;

    float* partS = (float*)(smem + OFF_PART);
    float* Hs    = (float*)(smem + OFF_H);
    float* Vs    = (float*)(smem + OFF_V);
    if (tid < 128) {
        Hs[tid] = g_H[b * ATT_ + nc * 128 + tid];
        Vs[tid] = V[nc * 128 + tid];
    }

    float d[2][8][4];
#pragma unroll
    for (int mt = 0; mt < 2; ++mt)
#pragma unroll
        for (int nt = 0; nt < 8; ++nt)
#pragma unroll
            for (int e = 0; e < 4; ++e) d[mt][nt][e] = 0.f;

    // cp: per tile 1024 x 16B -> 4/thread: j=tid+e*256, row=j>>3, q=j&7
    // A src chunk c: g_F16 + ((mb*32 + c)*128 + row)*64 + q*8
    // B src chunk c: g_B16 + ((c*512 + nc*128 + row))*64 + q*8

    // ---- prologue: chunk 0 -> stage 0 ----
#pragma unroll
    for (int e = 0; e < 4; ++e) {
        int j = tid + e * 256, row = j >> 3, q = j & 7;
        uint32_t dsto = (uint32_t)(row * PITCH + q * 16);
        size_t ao = (((size_t)(mb * 32 + 0) * 128 + row) << 6) + q * 8;
        size_t bo = (((size_t)(0 * 512 + nc * 128 + row)) << 6) + q * 8;
        cp16(sb + OFF_A + dsto, g_F16 + ao);
        cp16(sb + OFF_B + dsto, g_B16 + bo);
    }
    cp_commit();

    const uint32_t a_lrow = (uint32_t)(wm * 32 + (lane & 15));
    const uint32_t a_loff = (uint32_t)(((lane >> 4) & 1) * 16);
    const uint32_t b_prow = (uint32_t)(wn * 64 + (lane & 15));   // + p*16
    const uint32_t b_poff = (uint32_t)(((lane >> 4) & 1) * 16);

#pragma unroll 1
    for (int i = 0; i < ENC_ / 64; ++i) {
        const int s = i & 1;
        const uint32_t stg  = sb + s * STAGE;
        const uint32_t nstg = sb + (s ^ 1) * STAGE;

        cp_wait0();
        __syncthreads();   // stage s populated; all warps done reading s^1

        if (i + 1 < ENC_ / 64) {
#pragma unroll
            for (int e = 0; e < 4; ++e) {
                int j = tid + e * 256, row = j >> 3, q = j & 7;
                uint32_t dsto = (uint32_t)(row * PITCH + q * 16);
                size_t ao = (((size_t)(mb * 32 + i + 1) * 128 + row) << 6) + q * 8;
                size_t bo = (((size_t)((i + 1) * 512 + nc * 128 + row)) << 6) + q * 8;
                cp16(nstg + OFF_A + dsto, g_F16 + ao);
                cp16(nstg + OFF_B + dsto, g_B16 + bo);
            }
            cp_commit();
        }

        // ---- compute chunk i on stage s: 4 k16 slabs ----
#pragma unroll
        for (int kk = 0; kk < 4; ++kk) {
            const uint32_t ko = (uint32_t)(kk * 32);
            uint32_t a0[4], a1[4];
            ldsm_x4(a0, stg + OFF_A + a_lrow * PITCH + a_loff + ko);
            ldsm_x4(a1, stg + OFF_A + (a_lrow + 16) * PITCH + a_loff + ko);
            uint32_t bb[8][2];
#pragma unroll
            for (int p = 0; p < 4; ++p) {       // paired ldsm: 2 n-tiles per x4
                uint32_t r[4];
                ldsm_x4(r, stg + OFF_B + (b_prow + p * 16) * PITCH + b_poff + ko);
                bb[2 * p][0]     = r[0];
                bb[2 * p + 1][0] = r[1];
                bb[2 * p][1]     = r[2];
                bb[2 * p + 1][1] = r[3];
            }
#pragma unroll
            for (int nt = 0; nt < 8; ++nt) {
                mma_f16(d[0][nt], a0, bb[nt]);
                mma_f16(d[1][nt], a1, bb[nt]);
            }
        }
    }

    // ---- epilogue: tanh + V-weighted row reduction over this 128-col chunk ----
#pragma unroll
    for (int mt = 0; mt < 2; ++mt) {
        float s0 = 0.f, s1 = 0.f;
#pragma unroll
        for (int nt = 0; nt < 8; ++nt) {
            int c0 = wn * 64 + nt * 8 + (lane & 3) * 2;
            float h0 = Hs[c0], v0 = Vs[c0];
            float h1 = Hs[c0 + 1], v1 = Vs[c0 + 1];
            s0 += fast_tanh(d[mt][nt][0] + h0) * v0 + fast_tanh(d[mt][nt][1] + h1) * v1;
            s1 += fast_tanh(d[mt][nt][2] + h0) * v0 + fast_tanh(d[mt][nt][3] + h1) * v1;
        }
#pragma unroll
        for (int o = 1; o <= 2; o <<= 1) {
            s0 += __shfl_xor_sync(~0u, s0, o);
            s1 += __shfl_xor_sync(~0u, s1, o);
        }
        if ((lane & 3) == 0) {
            int r = wm * 32 + mt * 16 + (lane >> 2);
            partS[wn * 128 + r]     = s0;
            partS[wn * 128 + r + 8] = s1;
        }
    }
    __syncthreads();
    if (tid < 128)
        g_scorep[nc * BL_ + m0 + tid] = partS[tid] + partS[128 + tid];
}

// ---------------------------------------------------------------------------
// Kernel D: combine partials + softmax over L per batch
// ---------------------------------------------------------------------------
__global__ void softmax_kernel(const float* __restrict__ bv, float* __restrict__ w) {
    __shared__ float redm[32];
    __shared__ float reds[32];
    const int b = blockIdx.x, t = threadIdx.x;
    const int idx = b * L_ + t;
    float s = g_scorep[idx] + g_scorep[BL_ + idx] + g_scorep[2 * BL_ + idx] +
              g_scorep[3 * BL_ + idx] + bv[0];
    float m = s;
#pragma unroll
    for (int o = 16; o > 0; o >>= 1) m = fmaxf(m, __shfl_xor_sync(~0u, m, o));
    if ((t & 31) == 0) redm[t >> 5] = m;
    __syncthreads();
    if (t < 32) {
        float v = redm[t];
#pragma unroll
        for (int o = 16; o > 0; o >>= 1) v = fmaxf(v, __shfl_xor_sync(~0u, v, o));
        redm[t] = v;
    }
    __syncthreads();
    m = redm[0];
    const float e = expf(s - m);
    float sum = e;
#pragma unroll
    for (int o = 16; o > 0; o >>= 1) sum += __shfl_xor_sync(~0u, sum, o);
    if ((t & 31) == 0) reds[t >> 5] = sum;
    __syncthreads();
    if (t < 32) {
        float v = reds[t];
#pragma unroll
        for (int o = 16; o > 0; o >>= 1) v += __shfl_xor_sync(~0u, v, o);
        reds[t] = v;
    }
    __syncthreads();
    w[idx] = e / reds[0];
}

// ---------------------------------------------------------------------------
// Kernel E/F: context = sum_l w*F  (fp16 tiled F; 8 L-partials, then reduced)
// ---------------------------------------------------------------------------
__global__ void context_part_kernel(const float* __restrict__ w) {
    __shared__ float ws[128];
    const int b = blockIdx.y, z = blockIdx.z, t = threadIdx.x;
    ws[t] = w[b * L_ + z * 128 + t];
    __syncthreads();
    const int e0 = blockIdx.x * 512 + t * 4;
    const int mb = b * 8 + z;
    const int c  = e0 >> 6, kk = e0 & 63;
    const __half* base = g_F16 + (((size_t)(mb * 32 + c) * 128) << 6) + kk;
    float4 acc = make_float4(0.f, 0.f, 0.f, 0.f);
#pragma unroll 4
    for (int l = 0; l < 128; ++l) {
        uint2 v = *(const uint2*)(base + ((size_t)l << 6));
        float2 f01 = __half22float2(*(const __half2*)&v.x);
        float2 f23 = __half22float2(*(const __half2*)&v.y);
        const float wl = ws[l];
        acc.x += wl * f01.x; acc.y += wl * f01.y;
        acc.z += wl * f23.x; acc.w += wl * f23.y;
    }
    *(float4*)&g_ctxp[(size_t)(z * B_ + b) * ENC_ + e0] = acc;
}

__global__ void context_reduce_kernel(float* __restrict__ ctx) {
    const int i = (blockIdx.x * 256 + threadIdx.x) * 4;
    float4 acc = make_float4(0.f, 0.f, 0.f, 0.f);
#pragma unroll
    for (int p = 0; p < 8; ++p) {
        float4 a = *(const float4*)&g_ctxp[(size_t)p * B_ * ENC_ + i];
        acc.x += a.x; acc.y += a.y; acc.z += a.z; acc.w += a.w;
    }
    *(float4*)&ctx[i] = acc;
}

// ---------------------------------------------------------------------------
// Launch
// ---------------------------------------------------------------------------
extern "C" void kernel_launch(void* const* d_in, const int* in_sizes, int n_in,
                              void* d_out, int out_size) {
    const float* F   = (const float*)d_in[0];
    const float* hid = (const float*)d_in[1];
    const float* W1  = (const float*)d_in[2];
    const float* b1  = (const float*)d_in[3];
    const float* W2  = (const float*)d_in[4];
    const float* b2  = (const float*)d_in[5];
    const float* V   = (const float*)d_in[6];
    const float* bv  = (const float*)d_in[7];

    float* out = (float*)d_out;
    float* ctx = out;
    float* wts = out + B_ * ENC_;

    cudaFuncSetAttribute(score_mma_kernel,
                         cudaFuncAttributeMaxDynamicSharedMemorySize, SMEM_TOTAL);

    proj_h_kernel<<<B_, ATT_>>>(hid, W2, b2, b1);
    prep_B_kernel<<<(ENC_ * ATT_) / 256, 256>>>(W1);
    prep_F_kernel<<<(int)(((size_t)BL_ * ENC_ / 4) / 256), 256>>>(F);
    score_mma_kernel<<<dim3(4, BL_ / 128), 256, SMEM_TOTAL>>>(V);
    softmax_kernel<<<B_, L_>>>(bv, wts);
    context_part_kernel<<<dim3(ENC_ / 512, B_, 8), 128>>>(wts);
    context_reduce_kernel<<<(B_ * ENC_) / 1024, 256>>>(ctx);
}

// round 8
// speedup vs baseline: 2.3510x; 1.0213x over previous
#include <cuda_runtime.h>
#include <cuda_fp16.h>
#include <math.h>
#include <stdint.h>

#define B_   64
#define L_   1024
#define ENC_ 2048
#define DEC_ 512
#define ATT_ 512
#define BL_  (B_ * L_)

// ---------------------------------------------------------------------------
// Device scratch
// ---------------------------------------------------------------------------
__device__ float g_H[B_ * ATT_];                          // proj_h + b2 + b1
// W1 fp16, layout [c=k/64][n 512][k 64]
__device__ __align__(128) __half g_B16[ENC_ * ATT_];
// F fp16, layout [mb=row/128][c=k/64][row 128][k 64]
__device__ __align__(128) __half g_F16[(size_t)BL_ * ENC_];
__device__ float g_scorep[4 * BL_];                       // per-N-chunk score partials
__device__ float g_ctxp[8 * B_ * ENC_];                   // context partials

// ---------------------------------------------------------------------------
// Helpers
// ---------------------------------------------------------------------------
__device__ __forceinline__ uint32_t smem_u32(const void* p) {
    uint32_t a;
    asm("{ .reg .u64 t; cvta.to.shared.u64 t, %1; cvt.u32.u64 %0, t; }" : "=r"(a) : "l"(p));
    return a;
}
__device__ __forceinline__ void cp16(uint32_t dst, const void* src) {
    asm volatile("cp.async.cg.shared.global [%0], [%1], 16;" :: "r"(dst), "l"(src));
}
__device__ __forceinline__ void cp_commit() {
    asm volatile("cp.async.commit_group;" ::: "memory");
}
__device__ __forceinline__ void cp_wait1() {
    asm volatile("cp.async.wait_group 1;" ::: "memory");
}
__device__ __forceinline__ void ldsm_x4(uint32_t* r, uint32_t addr) {
    asm volatile("ldmatrix.sync.aligned.m8n8.x4.shared.b16 {%0,%1,%2,%3}, [%4];"
                 : "=r"(r[0]), "=r"(r[1]), "=r"(r[2]), "=r"(r[3]) : "r"(addr));
}
__device__ __forceinline__ void mma_f16(float* d, const uint32_t* a, const uint32_t* b) {
    asm volatile(
        "mma.sync.aligned.m16n8k16.row.col.f32.f16.f16.f32 "
        "{%0,%1,%2,%3}, {%4,%5,%6,%7}, {%8,%9}, {%0,%1,%2,%3};"
        : "+f"(d[0]), "+f"(d[1]), "+f"(d[2]), "+f"(d[3])
        : "r"(a[0]), "r"(a[1]), "r"(a[2]), "r"(a[3]), "r"(b[0]), "r"(b[1]));
}
__device__ __forceinline__ float fast_tanh(float x) {
    float e = __expf(2.f * x);
    return __fdividef(e - 1.f, e + 1.f);
}

// ---------------------------------------------------------------------------
// Kernel A: H = hidden @ W2 + b2 + b1
// ---------------------------------------------------------------------------
__global__ void proj_h_kernel(const float* __restrict__ hidden,
                              const float* __restrict__ W2,
                              const float* __restrict__ b2,
                              const float* __restrict__ b1) {
    __shared__ float hs[DEC_];
    int b = blockIdx.x, a = threadIdx.x;
    hs[a] = hidden[b * DEC_ + a];
    __syncthreads();
    float acc = 0.f;
#pragma unroll 8
    for (int d = 0; d < DEC_; ++d) acc += hs[d] * W2[d * ATT_ + a];
    g_H[b * ATT_ + a] = acc + b2[a] + b1[a];
}

// ---------------------------------------------------------------------------
// Kernel B1: W1 [ENC, ATT] fp32 -> fp16, layout [c][n][k64]
// ---------------------------------------------------------------------------
__global__ void prep_B_kernel(const float* __restrict__ W1) {
    int idx = blockIdx.x * 256 + threadIdx.x;   // idx = k*512 + n
    if (idx >= ENC_ * ATT_) return;
    int k = idx >> 9, n = idx & 511;
    int c = k >> 6, kk = k & 63;
    g_B16[((size_t)(c * 512 + n) << 6) + kk] = __float2half_rn(W1[idx]);
}

// ---------------------------------------------------------------------------
// Kernel B2: F [BL, ENC] fp32 -> fp16, layout [mb][c][row][k64]
// ---------------------------------------------------------------------------
__global__ void prep_F_kernel(const float* __restrict__ F) {
    size_t f4 = (size_t)blockIdx.x * 256 + threadIdx.x;  // float4 index
    size_t r  = f4 >> 9;            // global row (512 float4 per row)
    int   k   = (int)(f4 & 511) * 4;
    int   mb  = (int)(r >> 7), row = (int)(r & 127);
    int   c   = k >> 6, kk = k & 63;
    float4 f = *(const float4*)(F + (r << 11) + k);
    __half2 h01 = __floats2half2_rn(f.x, f.y);
    __half2 h23 = __floats2half2_rn(f.z, f.w);
    size_t o = (((size_t)(mb * 32 + c) * 128 + row) << 6) + kk;
    *(uint2*)(g_F16 + o) = make_uint2(*(uint32_t*)&h01, *(uint32_t*)&h23);
}

// ---------------------------------------------------------------------------
// Kernel C: fused fp16 mma.sync GEMM + tanh + V-reduction -> score partials
// Grid: (4 nc, 512 m) nc-major. CTA: 128x128, 256 thr, KC=64.
// 3-stage cp.async pipeline (wait_group 1), strength-reduced addressing.
// ---------------------------------------------------------------------------
static constexpr int PITCH  = 144;            // 128B data + 16B pad
static constexpr int TILE   = 128 * PITCH;    // 18432
static constexpr int STAGE  = 2 * TILE;       // A,B = 36864
static constexpr int NSTG   = 3;
static constexpr int OFF_A  = 0;
static constexpr int OFF_B  = TILE;
static constexpr int OFF_PART = NSTG * STAGE;         // 110592: 256 floats
static constexpr int OFF_H    = OFF_PART + 1024;
static constexpr int OFF_V    = OFF_H + 512;
static constexpr int SMEM_TOTAL = OFF_V + 512;        // 112640
static constexpr int NCHUNK = ENC_ / 64;              // 32
static constexpr int A_STRIDE = 128 * 64;             // halves per chunk
static constexpr int B_STRIDE = 512 * 64;

__global__ __launch_bounds__(256, 2) void score_mma_kernel(const float* __restrict__ V)
{
    extern __shared__ char smem[];
    const uint32_t sb = smem_u32(smem);
    const int tid  = threadIdx.x;
    const int lane = tid & 31;
    const int wid  = tid >> 5;
    const int wm   = wid & 3;        // warp m: 4 x 32 rows
    const int wn   = wid >> 2;       // warp n: 2 x 64 cols
    const int nc   = blockIdx.x;     // n chunk (128 cols)
    const int mb   = blockIdx.y;
    const int m0   = mb * 128;
    const int b    = mb >> 3;

    float* partS = (float*)(smem + OFF_PART);
    float* Hs    = (float*)(smem + OFF_H);
    float* Vs    = (float*)(smem + OFF_V);
    if (tid < 128) {
        Hs[tid] = g_H[b * ATT_ + nc * 128 + tid];
        Vs[tid] = V[nc * 128 + tid];
    }

    float d[2][8][4];
#pragma unroll
    for (int mt = 0; mt < 2; ++mt)
#pragma unroll
        for (int nt = 0; nt < 8; ++nt)
#pragma unroll
            for (int e = 0; e < 4; ++e) d[mt][nt][e] = 0.f;

    // strength-reduced prefetch state: 4 (dst offset, src pointer) pairs
    uint32_t dsto[4];
    const __half* pA[4];
    const __half* pB[4];
#pragma unroll
    for (int e = 0; e < 4; ++e) {
        int j = tid + e * 256, row = j >> 3, q = j & 7;
        dsto[e] = (uint32_t)(row * PITCH + q * 16);
        pA[e] = g_F16 + (((size_t)(mb * 32) * 128 + row) << 6) + q * 8;
        pB[e] = g_B16 + (((size_t)(nc * 128 + row)) << 6) + q * 8;
    }

    // ---- prologue: chunks 0,1 -> stages 0,1 (two commit groups) ----
#pragma unroll
    for (int c = 0; c < 2; ++c) {
        const uint32_t stg = sb + c * STAGE;
#pragma unroll
        for (int e = 0; e < 4; ++e) {
            cp16(stg + OFF_A + dsto[e], pA[e]);
            cp16(stg + OFF_B + dsto[e], pB[e]);
            pA[e] += A_STRIDE;
            pB[e] += B_STRIDE;
        }
        cp_commit();
    }

    // hoisted ldsm base offsets (stage-relative)
    const uint32_t aoff0 = OFF_A + (uint32_t)(wm * 32 + (lane & 15)) * PITCH +
                           (uint32_t)(((lane >> 4) & 1) * 16);
    const uint32_t aoff1 = aoff0 + 16 * PITCH;
    uint32_t boff[4];
#pragma unroll
    for (int p = 0; p < 4; ++p)
        boff[p] = OFF_B + (uint32_t)(wn * 64 + p * 16 + (lane & 15)) * PITCH +
                  (uint32_t)(((lane >> 4) & 1) * 16);

    int cs = 0, ps = 2;   // compute stage, prefetch stage
#pragma unroll 1
    for (int i = 0; i < NCHUNK; ++i) {
        const uint32_t stg = sb + cs * STAGE;
        if (++cs == NSTG) cs = 0;

        cp_wait1();        // chunk i complete (newest group may still fly)
        __syncthreads();   // all warps: data visible; prefetch buffer free

        if (i + 2 < NCHUNK) {
            const uint32_t nstg = sb + ps * STAGE;
            if (++ps == NSTG) ps = 0;
#pragma unroll
            for (int e = 0; e < 4; ++e) {
                cp16(nstg + OFF_A + dsto[e], pA[e]);
                cp16(nstg + OFF_B + dsto[e], pB[e]);
                pA[e] += A_STRIDE;
                pB[e] += B_STRIDE;
            }
            cp_commit();
        }

        // ---- compute chunk i on stage stg: 4 k16 slabs ----
#pragma unroll
        for (int kk = 0; kk < 4; ++kk) {
            const uint32_t ko = (uint32_t)(kk * 32);
            uint32_t a0[4], a1[4];
            ldsm_x4(a0, stg + aoff0 + ko);
            ldsm_x4(a1, stg + aoff1 + ko);
            uint32_t bb[8][2];
#pragma unroll
            for (int p = 0; p < 4; ++p) {       // paired ldsm: 2 n-tiles per x4
                uint32_t r[4];
                ldsm_x4(r, stg + boff[p] + ko);
                bb[2 * p][0]     = r[0];
                bb[2 * p + 1][0] = r[1];
                bb[2 * p][1]     = r[2];
                bb[2 * p + 1][1] = r[3];
            }
#pragma unroll
            for (int nt = 0; nt < 8; ++nt) {
                mma_f16(d[0][nt], a0, bb[nt]);
                mma_f16(d[1][nt], a1, bb[nt]);
            }
        }
    }

    // ---- epilogue: tanh + V-weighted row reduction over this 128-col chunk ----
#pragma unroll
    for (int mt = 0; mt < 2; ++mt) {
        float s0 = 0.f, s1 = 0.f;
#pragma unroll
        for (int nt = 0; nt < 8; ++nt) {
            int c0 = wn * 64 + nt * 8 + (lane & 3) * 2;
            float h0 = Hs[c0], v0 = Vs[c0];
            float h1 = Hs[c0 + 1], v1 = Vs[c0 + 1];
            s0 += fast_tanh(d[mt][nt][0] + h0) * v0 + fast_tanh(d[mt][nt][1] + h1) * v1;
            s1 += fast_tanh(d[mt][nt][2] + h0) * v0 + fast_tanh(d[mt][nt][3] + h1) * v1;
        }
#pragma unroll
        for (int o = 1; o <= 2; o <<= 1) {
            s0 += __shfl_xor_sync(~0u, s0, o);
            s1 += __shfl_xor_sync(~0u, s1, o);
        }
        if ((lane & 3) == 0) {
            int r = wm * 32 + mt * 16 + (lane >> 2);
            partS[wn * 128 + r]     = s0;
            partS[wn * 128 + r + 8] = s1;
        }
    }
    __syncthreads();
    if (tid < 128)
        g_scorep[nc * BL_ + m0 + tid] = partS[tid] + partS[128 + tid];
}

// ---------------------------------------------------------------------------
// Kernel D: combine partials + softmax over L per batch
// ---------------------------------------------------------------------------
__global__ void softmax_kernel(const float* __restrict__ bv, float* __restrict__ w) {
    __shared__ float redm[32];
    __shared__ float reds[32];
    const int b = blockIdx.x, t = threadIdx.x;
    const int idx = b * L_ + t;
    float s = g_scorep[idx] + g_scorep[BL_ + idx] + g_scorep[2 * BL_ + idx] +
              g_scorep[3 * BL_ + idx] + bv[0];
    float m = s;
#pragma unroll
    for (int o = 16; o > 0; o >>= 1) m = fmaxf(m, __shfl_xor_sync(~0u, m, o));
    if ((t & 31) == 0) redm[t >> 5] = m;
    __syncthreads();
    if (t < 32) {
        float v = redm[t];
#pragma unroll
        for (int o = 16; o > 0; o >>= 1) v = fmaxf(v, __shfl_xor_sync(~0u, v, o));
        redm[t] = v;
    }
    __syncthreads();
    m = redm[0];
    const float e = expf(s - m);
    float sum = e;
#pragma unroll
    for (int o = 16; o > 0; o >>= 1) sum += __shfl_xor_sync(~0u, sum, o);
    if ((t & 31) == 0) reds[t >> 5] = sum;
    __syncthreads();
    if (t < 32) {
        float v = reds[t];
#pragma unroll
        for (int o = 16; o > 0; o >>= 1) v += __shfl_xor_sync(~0u, v, o);
        reds[t] = v;
    }
    __syncthreads();
    w[idx] = e / reds[0];
}

// ---------------------------------------------------------------------------
// Kernel E/F: context = sum_l w*F  (fp16 tiled F; 8 L-partials, then reduced)
// ---------------------------------------------------------------------------
__global__ void context_part_kernel(const float* __restrict__ w) {
    __shared__ float ws[128];
    const int b = blockIdx.y, z = blockIdx.z, t = threadIdx.x;
    ws[t] = w[b * L_ + z * 128 + t];
    __syncthreads();
    const int e0 = blockIdx.x * 512 + t * 4;
    const int mb = b * 8 + z;
    const int c  = e0 >> 6, kk = e0 & 63;
    const __half* base = g_F16 + (((size_t)(mb * 32 + c) * 128) << 6) + kk;
    float4 acc = make_float4(0.f, 0.f, 0.f, 0.f);
#pragma unroll 4
    for (int l = 0; l < 128; ++l) {
        uint2 v = *(const uint2*)(base + ((size_t)l << 6));
        float2 f01 = __half22float2(*(const __half2*)&v.x);
        float2 f23 = __half22float2(*(const __half2*)&v.y);
        const float wl = ws[l];
        acc.x += wl * f01.x; acc.y += wl * f01.y;
        acc.z += wl * f23.x; acc.w += wl * f23.y;
    }
    *(float4*)&g_ctxp[(size_t)(z * B_ + b) * ENC_ + e0] = acc;
}

__global__ void context_reduce_kernel(float* __restrict__ ctx) {
    const int i = (blockIdx.x * 256 + threadIdx.x) * 4;
    float4 acc = make_float4(0.f, 0.f, 0.f, 0.f);
#pragma unroll
    for (int p = 0; p < 8; ++p) {
        float4 a = *(const float4*)&g_ctxp[(size_t)p * B_ * ENC_ + i];
        acc.x += a.x; acc.y += a.y; acc.z += a.z; acc.w += a.w;
    }
    *(float4*)&ctx[i] = acc;
}

// ---------------------------------------------------------------------------
// Launch
// ---------------------------------------------------------------------------
extern "C" void kernel_launch(void* const* d_in, const int* in_sizes, int n_in,
                              void* d_out, int out_size) {
    const float* F   = (const float*)d_in[0];
    const float* hid = (const float*)d_in[1];
    const float* W1  = (const float*)d_in[2];
    const float* b1  = (const float*)d_in[3];
    const float* W2  = (const float*)d_in[4];
    const float* b2  = (const float*)d_in[5];
    const float* V   = (const float*)d_in[6];
    const float* bv  = (const float*)d_in[7];

    float* out = (float*)d_out;
    float* ctx = out;
    float* wts = out + B_ * ENC_;

    cudaFuncSetAttribute(score_mma_kernel,
                         cudaFuncAttributeMaxDynamicSharedMemorySize, SMEM_TOTAL);

    proj_h_kernel<<<B_, ATT_>>>(hid, W2, b2, b1);
    prep_B_kernel<<<(ENC_ * ATT_) / 256, 256>>>(W1);
    prep_F_kernel<<<(int)(((size_t)BL_ * ENC_ / 4) / 256), 256>>>(F);
    score_mma_kernel<<<dim3(4, BL_ / 128), 256, SMEM_TOTAL>>>(V);
    softmax_kernel<<<B_, L_>>>(bv, wts);
    context_part_kernel<<<dim3(ENC_ / 512, B_, 8), 128>>>(wts);
    context_reduce_kernel<<<(B_ * ENC_) / 1024, 256>>>(ctx);
}